// round 14
// baseline (speedup 1.0000x reference)
#include <cuda_runtime.h>
#include <math.h>

#define HD   100
#define OBS  114
#define RPB  4          // warps per block (small blocks -> finer occupancy granularity)
#define R    4          // rows per warp
#define C2L  2.8853900817779268f   // 2*log2(e)

// per-row smem layout (float offsets); h aliases x[0:100] after f1
#define S_RAW 0         // 116 used (pad 120)
#define S_SE  120       // 100 (self-emb; u = g*q store during attention)
#define S_X   220       // 400 (gi|va|vl|vg); h overwrites [220,320) after f1
#define S_ST  620       // 32 (16 x float2 attn stats)
#define SROW  652
#define SMEM_BYTES (RPB * R * SROW * 4)    // 41,728 B/block -> 5 blocks/SM

typedef unsigned long long u64;
struct pf4 { u64 a, b; };   // packed f32x2 pair = 4 floats

// pre-scaled weights + packed attention tables (static device mem, no allocation)
__device__ float g_sW [4 * HD];
__device__ float g_fcW[HD * HD];
__device__ float g_f1W[4 * HD * HD];
__device__ float g_f2W[HD * HD];
__device__ float g_tbO[4 * HD];   // (c*w0, c*w1, c*b, 0)
__device__ float g_tbL[4 * HD];   // (c*w0, c*w1, c*w2, c*b)
__device__ float g_tbG[4 * HD];   // (c*w0, c*w1, c*b, 0)

__global__ void repack_kernel(const float* __restrict__ sW, const float* __restrict__ fcW,
                              const float* __restrict__ f1W, const float* __restrict__ f2W,
                              const float* __restrict__ oW, const float* __restrict__ ob,
                              const float* __restrict__ lW, const float* __restrict__ lb,
                              const float* __restrict__ gW, const float* __restrict__ gb) {
    int i = blockIdx.x * blockDim.x + threadIdx.x;
    if (i < 4 * HD)      g_sW[i]  = sW[i]  * C2L;
    if (i < HD * HD)     g_fcW[i] = fcW[i] * C2L;
    if (i < HD * HD)     g_f2W[i] = f2W[i] * C2L;
    if (i < 4 * HD * HD) g_f1W[i] = f1W[i] * C2L;
    if (i < HD) {
        g_tbO[4 * i + 0] = oW[i] * C2L;       g_tbO[4 * i + 1] = oW[HD + i] * C2L;
        g_tbO[4 * i + 2] = ob[i] * C2L;       g_tbO[4 * i + 3] = 0.f;
        g_tbL[4 * i + 0] = lW[i] * C2L;       g_tbL[4 * i + 1] = lW[HD + i] * C2L;
        g_tbL[4 * i + 2] = lW[2 * HD + i] * C2L; g_tbL[4 * i + 3] = lb[i] * C2L;
        g_tbG[4 * i + 0] = gW[i] * C2L;       g_tbG[4 * i + 1] = gW[HD + i] * C2L;
        g_tbG[4 * i + 2] = gb[i] * C2L;       g_tbG[4 * i + 3] = 0.f;
    }
}

__device__ __forceinline__ float4 ld4(const float* p) { return *reinterpret_cast<const float4*>(p); }
__device__ __forceinline__ void   st4(float* p, float4 v) { *reinterpret_cast<float4*>(p) = v; }
__device__ __forceinline__ float4 f4z() { return make_float4(0.f, 0.f, 0.f, 0.f); }
__device__ __forceinline__ pf4    pz()  { pf4 r; r.a = 0ull; r.b = 0ull; return r; }
__device__ __forceinline__ pf4 ldp(const float* p) {
    ulonglong2 v = *reinterpret_cast<const ulonglong2*>(p);
    pf4 r; r.a = v.x; r.b = v.y; return r;
}
__device__ __forceinline__ u64 pk(float s) {
    u64 d; asm("mov.b64 %0,{%1,%1};" : "=l"(d) : "f"(s)); return d;
}
__device__ __forceinline__ void fmap(u64 s, const pf4& w, pf4& acc) {
    asm("fma.rn.f32x2 %0,%2,%3,%0;\n\t"
        "fma.rn.f32x2 %1,%2,%4,%1;"
        : "+l"(acc.a), "+l"(acc.b) : "l"(s), "l"(w.a), "l"(w.b));
}
__device__ __forceinline__ pf4 sclp(pf4 p, u64 c) {
    asm("mul.rn.f32x2 %0,%0,%2;\n\t"
        "mul.rn.f32x2 %1,%1,%2;"
        : "+l"(p.a), "+l"(p.b) : "l"(c));
    return p;
}
__device__ __forceinline__ float4 upk(const pf4& p) {
    float4 v;
    asm("mov.b64 {%0,%1},%2;" : "=f"(v.x), "=f"(v.y) : "l"(p.a));
    asm("mov.b64 {%0,%1},%2;" : "=f"(v.z), "=f"(v.w) : "l"(p.b));
    return v;
}
__device__ __forceinline__ float getc(float4 v, int k) {
    return k == 0 ? v.x : (k == 1 ? v.y : (k == 2 ? v.z : v.w));
}
__device__ __forceinline__ float4 fma4(float s, float4 w, float4 a) {
    a.x = fmaf(s, w.x, a.x); a.y = fmaf(s, w.y, a.y);
    a.z = fmaf(s, w.z, a.z); a.w = fmaf(s, w.w, a.w);
    return a;
}
__device__ __forceinline__ float hsum4(float4 v) { return (v.x + v.y) + (v.z + v.w); }
__device__ __forceinline__ float dot4(float4 a, float4 b) {
    return fmaf(a.x, b.x, fmaf(a.y, b.y, fmaf(a.z, b.z, a.w * b.w)));
}
// butterfly warp reductions (redux.sync.f32 does NOT exist on sm_103)
__device__ __forceinline__ float wsum(float v) {
#pragma unroll
    for (int o = 16; o; o >>= 1) v += __shfl_xor_sync(0xffffffffu, v, o);
    return v;
}
__device__ __forceinline__ float ex2a(float x) { float y; asm("ex2.approx.f32 %0,%1;" : "=f"(y) : "f"(x)); return y; }
__device__ __forceinline__ float rcpa(float x) { float y; asm("rcp.approx.f32 %0,%1;" : "=f"(y) : "f"(x)); return y; }
// tanh of pre-scaled input ps = 2*log2(e)*x
__device__ __forceinline__ float tanhp(float ps) {
    float e = ex2a(ps);
    return fmaf(-2.f, rcpa(1.f + e), 1.f);
}
__device__ __forceinline__ float4 tanh4p(float4 v) {
    v.x = tanhp(v.x); v.y = tanhp(v.y); v.z = tanhp(v.z); v.w = tanhp(v.w);
    return v;
}
// LayerNorm over 100 features on lanes 0..24 (4 each)
__device__ __forceinline__ float4 ln4(float4 pre, float4 g, float4 b, bool act) {
    float s  = act ? hsum4(pre) : 0.f;
    float sq = act ? dot4(pre, pre) : 0.f;
    s = wsum(s); sq = wsum(sq);
    float m = s * 0.01f;
    float r = rsqrtf(sq * 0.01f - m * m + 1e-5f);
    float4 o;
    o.x = (pre.x - m) * r * g.x + b.x;
    o.y = (pre.y - m) * r * g.y + b.y;
    o.z = (pre.z - m) * r * g.z + b.z;
    o.w = (pre.w - m) * r * g.w + b.w;
    return o;
}

// Attention head, 2 rows; transposed pass 1 (tables in global, L1-resident broadcast),
// j-layout pass 2.
template<int IN, int NN>
__device__ void attn_head(float* s0, float* s1, const float* tbl,
                          float4 q0, float4 q1, int rawOff,
                          const float* W, const float* Bv, const float* G, const float* BE,
                          int xoff, bool act, int lane, int j0)
{
    const u64 cc = pk(C2L);
    pf4 w[IN], bp = pz();
    float4 g4 = f4z(), be4 = f4z();
#pragma unroll
    for (int i = 0; i < IN; i++) w[i] = pz();
    float4 u0 = f4z(), u1 = f4z();
    if (act) {
#pragma unroll
        for (int i = 0; i < IN; i++) w[i] = sclp(ldp(W + i * HD + j0), cc);
        bp = sclp(ldp(Bv + j0), cc);
        g4 = ld4(G + j0); be4 = ld4(BE + j0);
        u0 = make_float4(g4.x * q0.x, g4.y * q0.y, g4.z * q0.z, g4.w * q0.w);
        u1 = make_float4(g4.x * q1.x, g4.y * q1.y, g4.z * q1.z, g4.w * q1.w);
        st4(s0 + S_SE + j0, u0); st4(s1 + S_SE + j0, u1);
    }
    float U0 = wsum(hsum4(u0));
    float U1 = wsum(hsum4(u1));
    float C0 = wsum(dot4(q0, be4));
    float C1 = wsum(dot4(q1, be4));
    __syncwarp();

    // pass 1 transposed: lane = encoder instance
    {
        const int gn = lane & 15;
        float* bs = (lane < 16) ? s0 : s1;
        const float Uq = (lane < 16) ? U0 : U1;
        const float Cq = (lane < 16) ? C0 : C1;
        float iv[IN];
#pragma unroll
        for (int i = 0; i < IN; i++) iv[i] = bs[rawOff + IN * gn + i];
        float a = 0.f, vv = 0.f, d = 0.f;
#pragma unroll 4
        for (int j = 0; j < HD; j++) {
            float4 T = ld4(tbl + 4 * j);
            float uj = bs[S_SE + j];
            float ps;
            if (IN == 2) ps = fmaf(iv[0], T.x, fmaf(iv[1], T.y, T.z));
            else         ps = fmaf(iv[0], T.x, fmaf(iv[1], T.y, fmaf(iv[2], T.z, T.w)));
            float t = tanhp(ps);
            a += t;
            vv = fmaf(t, t, vv);
            d  = fmaf(uj, t, d);
        }
        float m = a * 0.01f;
        float r = rsqrtf(vv * 0.01f - m * m + 1e-5f);
        float l = (gn < NN) ? fmaf(r, d - m * Uq, Cq) : -1e30f;
        const float LOG2E = 1.4426950408889634f;
        float mx = l;
#pragma unroll
        for (int o = 8; o; o >>= 1) mx = fmaxf(mx, __shfl_xor_sync(0xffffffffu, mx, o));
        float e = (gn < NN) ? ex2a((l - mx) * LOG2E) : 0.f;
        float den = e;
#pragma unroll
        for (int o = 8; o; o >>= 1) den += __shfl_xor_sync(0xffffffffu, den, o);
        if (gn < NN) {
            float c = e * rcpa(den) * r;
            *reinterpret_cast<float2*>(bs + S_ST + 2 * gn) = make_float2(m, c);
        }
    }
    __syncwarp();

    // pass 2: j-layout recompute + weighted accumulate
    float4 A0 = f4z(), A1 = f4z();
    float K0 = 0.f, K1 = 0.f;
    for (int n = 0; n < NN; n++) {
        float2 st0 = *reinterpret_cast<const float2*>(s0 + S_ST + 2 * n);
        float2 st1 = *reinterpret_cast<const float2*>(s1 + S_ST + 2 * n);
        pf4 p0 = bp, p1 = bp;
#pragma unroll
        for (int i = 0; i < IN; i++) {
            fmap(pk(s0[rawOff + IN * n + i]), w[i], p0);
            fmap(pk(s1[rawOff + IN * n + i]), w[i], p1);
        }
        float4 t0 = tanh4p(upk(p0)), t1 = tanh4p(upk(p1));
        A0 = fma4(st0.y, t0, A0);
        A1 = fma4(st1.y, t1, A1);
        K0 = fmaf(st0.y, st0.x, K0);
        K1 = fmaf(st1.y, st1.x, K1);
    }
    if (act) {
        float4 o0, o1;
        o0.x = fmaf(g4.x, A0.x - K0, be4.x); o0.y = fmaf(g4.y, A0.y - K0, be4.y);
        o0.z = fmaf(g4.z, A0.z - K0, be4.z); o0.w = fmaf(g4.w, A0.w - K0, be4.w);
        o1.x = fmaf(g4.x, A1.x - K1, be4.x); o1.y = fmaf(g4.y, A1.y - K1, be4.y);
        o1.z = fmaf(g4.z, A1.z - K1, be4.z); o1.w = fmaf(g4.w, A1.w - K1, be4.w);
        st4(s0 + S_X + xoff + j0, o0);
        st4(s1 + S_X + xoff + j0, o1);
    }
    __syncwarp();
}

extern __shared__ float smem[];

__global__ void __launch_bounds__(RPB * 32, 5) obsenc_kernel(
    const float* __restrict__ inp, int B,
    const float* __restrict__ sb,  const float* __restrict__ sg,  const float* __restrict__ sbe,
    const float* __restrict__ oW,  const float* __restrict__ ob,  const float* __restrict__ og,  const float* __restrict__ obe,
    const float* __restrict__ lW,  const float* __restrict__ lb,  const float* __restrict__ lg,  const float* __restrict__ lbe,
    const float* __restrict__ gW,  const float* __restrict__ gb,  const float* __restrict__ gg,  const float* __restrict__ gbe,
    const float* __restrict__ Ac,  const float* __restrict__ Lc,
    const float* __restrict__ fcb, const float* __restrict__ fcg, const float* __restrict__ fcbe,
    const float* __restrict__ f1b, const float* __restrict__ f1g, const float* __restrict__ f1be,
    const float* __restrict__ f2b, const float* __restrict__ f2g, const float* __restrict__ f2be,
    float* __restrict__ out)
{
    const u64 cc = pk(C2L);
    const int warp = threadIdx.x >> 5;
    const int lane = threadIdx.x & 31;
    const int row0 = (blockIdx.x * RPB + warp) * R;
    if (row0 >= B) return;

    float* s[R];
    int rows[R];
#pragma unroll
    for (int r = 0; r < R; r++) {
        rows[r] = min(row0 + r, B - 1);
        s[r] = smem + (warp * R + r) * SROW;
    }
    const bool act = lane < 25;
    const int  j0  = lane * 4;

    // ---- raw rows -> smem ----
#pragma unroll
    for (int r = 0; r < R; r++) {
        const float* p = inp + (long)rows[r] * OBS;
        for (int i = lane; i < OBS; i += 32) s[r][S_RAW + i] = p[i];
    }
    __syncwarp();

    // ---- self encoder: 4 -> 100 (g_sW pre-scaled) ----
    {
        pf4 w0 = pz(), w1 = pz(), w2 = pz(), w3 = pz(), bp = pz();
        float4 g4 = f4z(), be4 = f4z();
        if (act) {
            w0 = ldp(g_sW + j0); w1 = ldp(g_sW + HD + j0); w2 = ldp(g_sW + 2 * HD + j0); w3 = ldp(g_sW + 3 * HD + j0);
            bp = sclp(ldp(sb + j0), cc);
            g4 = ld4(sg + j0); be4 = ld4(sbe + j0);
        }
#pragma unroll
        for (int r = 0; r < R; r++) {
            pf4 p = bp;
            fmap(pk(s[r][S_RAW + 0]), w0, p);
            fmap(pk(s[r][S_RAW + 1]), w1, p);
            fmap(pk(s[r][S_RAW + 2]), w2, p);
            fmap(pk(s[r][S_RAW + 3]), w3, p);
            float4 e = ln4(tanh4p(upk(p)), g4, be4, act);
            if (act) st4(s[r] + S_SE + j0, e);
        }
    }
    __syncwarp();

    // ---- matvec pair (4-row blocked, packed): qa = se@Ac, ql = se@Lc ----
    pf4 qa[R], ql[R];
#pragma unroll
    for (int r = 0; r < R; r++) { qa[r] = pz(); ql[r] = pz(); }
    if (act) {
#pragma unroll 2
        for (int k4 = 0; k4 < 25; k4++) {
            float4 xv[R];
#pragma unroll
            for (int r = 0; r < R; r++) xv[r] = ld4(s[r] + S_SE + 4 * k4);
#pragma unroll
            for (int kk = 0; kk < 4; kk++) {
                const int k = 4 * k4 + kk;
                pf4 wa = ldp(Ac + k * HD + j0);
                pf4 wl = ldp(Lc + k * HD + j0);
#pragma unroll
                for (int r = 0; r < R; r++) {
                    u64 xs = pk(getc(xv[r], kk));
                    fmap(xs, wa, qa[r]);
                    fmap(xs, wl, ql[r]);
                }
            }
        }
    }
    // ---- fc matvec: gp = se@fcW' -> gi -> x[0:100] ----
    {
        pf4 gp[R];
        pf4 bpfc = pz();
        if (act) bpfc = sclp(ldp(fcb + j0), cc);
#pragma unroll
        for (int r = 0; r < R; r++) gp[r] = bpfc;
        if (act) {
#pragma unroll 2
            for (int k4 = 0; k4 < 25; k4++) {
                float4 xv[R];
#pragma unroll
                for (int r = 0; r < R; r++) xv[r] = ld4(s[r] + S_SE + 4 * k4);
#pragma unroll
                for (int kk = 0; kk < 4; kk++) {
                    pf4 wf = ldp(g_fcW + (4 * k4 + kk) * HD + j0);
#pragma unroll
                    for (int r = 0; r < R; r++) fmap(pk(getc(xv[r], kk)), wf, gp[r]);
                }
            }
        }
        float4 g4 = f4z(), b4 = f4z();
        if (act) { g4 = ld4(fcg + j0); b4 = ld4(fcbe + j0); }
#pragma unroll
        for (int r = 0; r < R; r++) {
            float4 gi = ln4(tanh4p(upk(gp[r])), g4, b4, act);
            if (act) st4(s[r] + S_X + j0, gi);
        }
    }
    __syncwarp();

    // ---- attention heads (2 rows per call; ql reused for goal head: source bug preserved) ----
    {
        float4 qaF[R], qlF[R];
#pragma unroll
        for (int r = 0; r < R; r++) { qaF[r] = upk(qa[r]); qlF[r] = upk(ql[r]); }
        attn_head<2, 15>(s[0], s[1], g_tbO, qaF[0], qaF[1], S_RAW + 52, oW, ob, og, obe, 100, act, lane, j0);
        attn_head<2, 15>(s[2], s[3], g_tbO, qaF[2], qaF[3], S_RAW + 52, oW, ob, og, obe, 100, act, lane, j0);
        attn_head<3, 16>(s[0], s[1], g_tbL, qlF[0], qlF[1], S_RAW + 4,  lW, lb, lg, lbe, 200, act, lane, j0);
        attn_head<3, 16>(s[2], s[3], g_tbL, qlF[2], qlF[3], S_RAW + 4,  lW, lb, lg, lbe, 200, act, lane, j0);
        attn_head<2, 16>(s[0], s[1], g_tbG, qlF[0], qlF[1], S_RAW + 82, gW, gb, gg, gbe, 300, act, lane, j0);
        attn_head<2, 16>(s[2], s[3], g_tbG, qlF[2], qlF[3], S_RAW + 82, gW, gb, gg, gbe, 300, act, lane, j0);
    }

    // ---- f1: 400 -> 100 (4-row blocked, packed, g_f1W pre-scaled) ----
    {
        pf4 a[R];
#pragma unroll
        for (int r = 0; r < R; r++) a[r] = pz();
        if (act) {
            pf4 bp = sclp(ldp(f1b + j0), cc);
#pragma unroll
            for (int r = 0; r < R; r++) a[r] = bp;
#pragma unroll 2
            for (int k4 = 0; k4 < 100; k4++) {
                float4 xv[R];
#pragma unroll
                for (int r = 0; r < R; r++) xv[r] = ld4(s[r] + S_X + 4 * k4);
#pragma unroll
                for (int kk = 0; kk < 4; kk++) {
                    pf4 w = ldp(g_f1W + (4 * k4 + kk) * HD + j0);
#pragma unroll
                    for (int r = 0; r < R; r++) fmap(pk(getc(xv[r], kk)), w, a[r]);
                }
            }
        }
        float4 g4 = f4z(), b4 = f4z();
        if (act) { g4 = ld4(f1g + j0); b4 = ld4(f1be + j0); }
        // h -> aliases x[0:100] (x fully consumed; rows are warp-private)
#pragma unroll
        for (int r = 0; r < R; r++) {
            float4 h = ln4(tanh4p(upk(a[r])), g4, b4, act);
            if (act) st4(s[r] + S_X + j0, h);
        }
    }
    __syncwarp();

    // ---- f2: 100 -> 100 -> out (g_f2W pre-scaled) ----
    {
        pf4 a[R];
#pragma unroll
        for (int r = 0; r < R; r++) a[r] = pz();
        if (act) {
            pf4 bp = sclp(ldp(f2b + j0), cc);
#pragma unroll
            for (int r = 0; r < R; r++) a[r] = bp;
#pragma unroll 2
            for (int k4 = 0; k4 < 25; k4++) {
                float4 xv[R];
#pragma unroll
                for (int r = 0; r < R; r++) xv[r] = ld4(s[r] + S_X + 4 * k4);
#pragma unroll
                for (int kk = 0; kk < 4; kk++) {
                    pf4 w = ldp(g_f2W + (4 * k4 + kk) * HD + j0);
#pragma unroll
                    for (int r = 0; r < R; r++) fmap(pk(getc(xv[r], kk)), w, a[r]);
                }
            }
        }
        float4 g4 = f4z(), b4 = f4z();
        if (act) { g4 = ld4(f2g + j0); b4 = ld4(f2be + j0); }
#pragma unroll
        for (int r = 0; r < R; r++) {
            float4 o = ln4(tanh4p(upk(a[r])), g4, b4, act);
            if (act) st4(out + (long)rows[r] * HD + j0, o);
        }
    }
}

extern "C" void kernel_launch(void* const* d_in, const int* in_sizes, int n_in,
                              void* d_out, int out_size) {
    const float* inp = (const float*)d_in[0];
    const int B = in_sizes[0] / OBS;

    // pre-scale tanh-feeding weights + pack attention tables
    repack_kernel<<<(4 * HD * HD + 255) / 256, 256>>>(
        (const float*)d_in[2], (const float*)d_in[20],
        (const float*)d_in[24], (const float*)d_in[28],
        (const float*)d_in[6],  (const float*)d_in[7],
        (const float*)d_in[10], (const float*)d_in[11],
        (const float*)d_in[14], (const float*)d_in[15]);

    cudaFuncSetAttribute(obsenc_kernel, cudaFuncAttributeMaxDynamicSharedMemorySize, SMEM_BYTES);

    const int rowsPerBlock = RPB * R;
    dim3 grid((B + rowsPerBlock - 1) / rowsPerBlock);
    obsenc_kernel<<<grid, RPB * 32, SMEM_BYTES>>>(
        inp, B,
        (const float*)d_in[3],  (const float*)d_in[4],  (const float*)d_in[5],
        (const float*)d_in[6],  (const float*)d_in[7],  (const float*)d_in[8],  (const float*)d_in[9],
        (const float*)d_in[10], (const float*)d_in[11], (const float*)d_in[12], (const float*)d_in[13],
        (const float*)d_in[14], (const float*)d_in[15], (const float*)d_in[16], (const float*)d_in[17],
        (const float*)d_in[18], (const float*)d_in[19],
        (const float*)d_in[21], (const float*)d_in[22], (const float*)d_in[23],
        (const float*)d_in[25], (const float*)d_in[26], (const float*)d_in[27],
        (const float*)d_in[29], (const float*)d_in[30], (const float*)d_in[31],
        (float*)d_out);
}

// round 16
// speedup vs baseline: 1.3510x; 1.3510x over previous
#include <cuda_runtime.h>
#include <math.h>

#define HD   100
#define OBS  114
#define RPB  8          // warps per block
#define R    4          // rows per warp

// block-shared packed attention weight tables (float offsets in smem)
#define TB_O  0         // oth: 100 x float4 (w0, w1, b, -)
#define TB_L  400       // lm : 100 x float4 (w0, w1, w2, b)
#define TB_G  800       // gl : 100 x float4 (w0, w1, b, -)
#define RBASE 1200      // per-row regions start (16B aligned)

// per-row smem layout (float offsets)
#define S_RAW 0         // 116 used
#define S_SE  120       // 100 (self-emb; u = g*q store during attention; dead after)
#define S_X   220       // 400 (gi|va|vl|vg)
#define S_H   620       // 100
#define S_ST  720       // 32 (16 x float2 attn stats)
#define SROW  752       // floats per row (16B-aligned)
#define SMEM_BYTES ((RBASE + RPB * R * SROW) * 4)

typedef unsigned long long u64;
struct pf4 { u64 a, b; };   // packed f32x2 pair = 4 floats

__device__ __forceinline__ float4 ld4(const float* p) { return *reinterpret_cast<const float4*>(p); }
__device__ __forceinline__ void   st4(float* p, float4 v) { *reinterpret_cast<float4*>(p) = v; }
__device__ __forceinline__ float4 f4z() { return make_float4(0.f, 0.f, 0.f, 0.f); }
__device__ __forceinline__ pf4    pz()  { pf4 r; r.a = 0ull; r.b = 0ull; return r; }
__device__ __forceinline__ pf4 ldp(const float* p) {
    ulonglong2 v = *reinterpret_cast<const ulonglong2*>(p);
    pf4 r; r.a = v.x; r.b = v.y; return r;
}
__device__ __forceinline__ u64 pk(float s) {
    u64 d; asm("mov.b64 %0,{%1,%1};" : "=l"(d) : "f"(s)); return d;
}
__device__ __forceinline__ void fmap(u64 s, const pf4& w, pf4& acc) {
    asm("fma.rn.f32x2 %0,%2,%3,%0;\n\t"
        "fma.rn.f32x2 %1,%2,%4,%1;"
        : "+l"(acc.a), "+l"(acc.b) : "l"(s), "l"(w.a), "l"(w.b));
}
__device__ __forceinline__ float4 upk(const pf4& p) {
    float4 v;
    asm("mov.b64 {%0,%1},%2;" : "=f"(v.x), "=f"(v.y) : "l"(p.a));
    asm("mov.b64 {%0,%1},%2;" : "=f"(v.z), "=f"(v.w) : "l"(p.b));
    return v;
}
__device__ __forceinline__ float getc(float4 v, int k) {
    return k == 0 ? v.x : (k == 1 ? v.y : (k == 2 ? v.z : v.w));
}
__device__ __forceinline__ float4 fma4(float s, float4 w, float4 a) {
    a.x = fmaf(s, w.x, a.x); a.y = fmaf(s, w.y, a.y);
    a.z = fmaf(s, w.z, a.z); a.w = fmaf(s, w.w, a.w);
    return a;
}
__device__ __forceinline__ float hsum4(float4 v) { return (v.x + v.y) + (v.z + v.w); }
__device__ __forceinline__ float dot4(float4 a, float4 b) {
    return fmaf(a.x, b.x, fmaf(a.y, b.y, fmaf(a.z, b.z, a.w * b.w)));
}
// butterfly warp reductions (redux.sync.f32 does NOT exist on sm_103)
__device__ __forceinline__ float wsum(float v) {
#pragma unroll
    for (int o = 16; o; o >>= 1) v += __shfl_xor_sync(0xffffffffu, v, o);
    return v;
}
__device__ __forceinline__ float ex2a(float x) { float y; asm("ex2.approx.f32 %0,%1;" : "=f"(y) : "f"(x)); return y; }
__device__ __forceinline__ float rcpa(float x) { float y; asm("rcp.approx.f32 %0,%1;" : "=f"(y) : "f"(x)); return y; }
// HW tanh: single MUFU op (sm_75+), max abs err ~1e-4
__device__ __forceinline__ float tanhhw(float x) {
    float y; asm("tanh.approx.f32 %0,%1;" : "=f"(y) : "f"(x)); return y;
}
__device__ __forceinline__ float4 tanh4h(float4 v) {
    v.x = tanhhw(v.x); v.y = tanhhw(v.y); v.z = tanhhw(v.z); v.w = tanhhw(v.w);
    return v;
}
// LayerNorm over 100 features on lanes 0..24 (4 each)
__device__ __forceinline__ float4 ln4(float4 pre, float4 g, float4 b, bool act) {
    float s  = act ? hsum4(pre) : 0.f;
    float sq = act ? dot4(pre, pre) : 0.f;
    s = wsum(s); sq = wsum(sq);
    float m = s * 0.01f;
    float r = rsqrtf(sq * 0.01f - m * m + 1e-5f);
    float4 o;
    o.x = (pre.x - m) * r * g.x + b.x;
    o.y = (pre.y - m) * r * g.y + b.y;
    o.z = (pre.z - m) * r * g.z + b.z;
    o.w = (pre.w - m) * r * g.w + b.w;
    return o;
}

// Attention head, 2 rows; transposed pass 1, j-layout pass 2 (R10-proven structure).
template<int IN, int NN>
__device__ void attn_head(float* s0, float* s1, const float* tbl,
                          float4 q0, float4 q1, int rawOff,
                          const float* W, const float* Bv, const float* G, const float* BE,
                          int xoff, bool act, int lane, int j0)
{
    pf4 w[IN], bp = pz();
    float4 g4 = f4z(), be4 = f4z();
#pragma unroll
    for (int i = 0; i < IN; i++) w[i] = pz();
    float4 u0 = f4z(), u1 = f4z();
    if (act) {
#pragma unroll
        for (int i = 0; i < IN; i++) w[i] = ldp(W + i * HD + j0);
        bp = ldp(Bv + j0);
        g4 = ld4(G + j0); be4 = ld4(BE + j0);
        u0 = make_float4(g4.x * q0.x, g4.y * q0.y, g4.z * q0.z, g4.w * q0.w);
        u1 = make_float4(g4.x * q1.x, g4.y * q1.y, g4.z * q1.z, g4.w * q1.w);
        st4(s0 + S_SE + j0, u0); st4(s1 + S_SE + j0, u1);
    }
    float U0 = wsum(hsum4(u0));
    float U1 = wsum(hsum4(u1));
    float C0 = wsum(dot4(q0, be4));
    float C1 = wsum(dot4(q1, be4));
    __syncwarp();   // u stores visible before transposed reads

    // pass 1 transposed: lane = encoder instance
    {
        const int gn = lane & 15;
        float* bs = (lane < 16) ? s0 : s1;
        const float Uq = (lane < 16) ? U0 : U1;
        const float Cq = (lane < 16) ? C0 : C1;
        float iv[IN];
#pragma unroll
        for (int i = 0; i < IN; i++) iv[i] = bs[rawOff + IN * gn + i];
        float a = 0.f, vv = 0.f, d = 0.f;
#pragma unroll 4
        for (int j = 0; j < HD; j++) {
            float4 T = ld4(tbl + 4 * j);
            float uj = bs[S_SE + j];
            float ps;
            if (IN == 2) ps = fmaf(iv[0], T.x, fmaf(iv[1], T.y, T.z));
            else         ps = fmaf(iv[0], T.x, fmaf(iv[1], T.y, fmaf(iv[2], T.z, T.w)));
            float t = tanhhw(ps);
            a += t;
            vv = fmaf(t, t, vv);
            d  = fmaf(uj, t, d);
        }
        float m = a * 0.01f;
        float r = rsqrtf(vv * 0.01f - m * m + 1e-5f);
        float l = (gn < NN) ? fmaf(r, d - m * Uq, Cq) : -1e30f;
        const float LOG2E = 1.4426950408889634f;
        float mx = l;
#pragma unroll
        for (int o = 8; o; o >>= 1) mx = fmaxf(mx, __shfl_xor_sync(0xffffffffu, mx, o));
        float e = (gn < NN) ? ex2a((l - mx) * LOG2E) : 0.f;
        float den = e;
#pragma unroll
        for (int o = 8; o; o >>= 1) den += __shfl_xor_sync(0xffffffffu, den, o);
        if (gn < NN) {
            float c = e * rcpa(den) * r;
            *reinterpret_cast<float2*>(bs + S_ST + 2 * gn) = make_float2(m, c);
        }
    }
    __syncwarp();

    // pass 2: j-layout recompute + weighted accumulate
    float4 A0 = f4z(), A1 = f4z();
    float K0 = 0.f, K1 = 0.f;
    for (int n = 0; n < NN; n++) {
        float2 st0 = *reinterpret_cast<const float2*>(s0 + S_ST + 2 * n);
        float2 st1 = *reinterpret_cast<const float2*>(s1 + S_ST + 2 * n);
        pf4 p0 = bp, p1 = bp;
#pragma unroll
        for (int i = 0; i < IN; i++) {
            fmap(pk(s0[rawOff + IN * n + i]), w[i], p0);
            fmap(pk(s1[rawOff + IN * n + i]), w[i], p1);
        }
        float4 t0 = tanh4h(upk(p0)), t1 = tanh4h(upk(p1));
        A0 = fma4(st0.y, t0, A0);
        A1 = fma4(st1.y, t1, A1);
        K0 = fmaf(st0.y, st0.x, K0);
        K1 = fmaf(st1.y, st1.x, K1);
    }
    if (act) {
        float4 o0, o1;
        o0.x = fmaf(g4.x, A0.x - K0, be4.x); o0.y = fmaf(g4.y, A0.y - K0, be4.y);
        o0.z = fmaf(g4.z, A0.z - K0, be4.z); o0.w = fmaf(g4.w, A0.w - K0, be4.w);
        o1.x = fmaf(g4.x, A1.x - K1, be4.x); o1.y = fmaf(g4.y, A1.y - K1, be4.y);
        o1.z = fmaf(g4.z, A1.z - K1, be4.z); o1.w = fmaf(g4.w, A1.w - K1, be4.w);
        st4(s0 + S_X + xoff + j0, o0);
        st4(s1 + S_X + xoff + j0, o1);
    }
    __syncwarp();
}

extern __shared__ float smem[];

__global__ void __launch_bounds__(RPB * 32, 2) obsenc_kernel(
    const float* __restrict__ inp, int B,
    const float* __restrict__ sW,  const float* __restrict__ sb,  const float* __restrict__ sg,  const float* __restrict__ sbe,
    const float* __restrict__ oW,  const float* __restrict__ ob,  const float* __restrict__ og,  const float* __restrict__ obe,
    const float* __restrict__ lW,  const float* __restrict__ lb,  const float* __restrict__ lg,  const float* __restrict__ lbe,
    const float* __restrict__ gW,  const float* __restrict__ gb,  const float* __restrict__ gg,  const float* __restrict__ gbe,
    const float* __restrict__ Ac,  const float* __restrict__ Lc,
    const float* __restrict__ fcW, const float* __restrict__ fcb, const float* __restrict__ fcg, const float* __restrict__ fcbe,
    const float* __restrict__ f1W, const float* __restrict__ f1b, const float* __restrict__ f1g, const float* __restrict__ f1be,
    const float* __restrict__ f2W, const float* __restrict__ f2b, const float* __restrict__ f2g, const float* __restrict__ f2be,
    float* __restrict__ out)
{
    // ---- stage packed attention weight tables (block-shared, raw weights) ----
    for (int j = threadIdx.x; j < HD; j += RPB * 32) {
        st4(smem + TB_O + 4 * j, make_float4(oW[j], oW[HD + j], ob[j], 0.f));
        st4(smem + TB_L + 4 * j, make_float4(lW[j], lW[HD + j], lW[2 * HD + j], lb[j]));
        st4(smem + TB_G + 4 * j, make_float4(gW[j], gW[HD + j], gb[j], 0.f));
    }
    __syncthreads();

    const int warp = threadIdx.x >> 5;
    const int lane = threadIdx.x & 31;
    const int row0 = (blockIdx.x * RPB + warp) * R;
    if (row0 >= B) return;

    float* s[R];
    int rows[R];
#pragma unroll
    for (int r = 0; r < R; r++) {
        rows[r] = min(row0 + r, B - 1);
        s[r] = smem + RBASE + (warp * R + r) * SROW;
    }
    const bool act = lane < 25;
    const int  j0  = lane * 4;

    // ---- raw rows -> smem ----
#pragma unroll
    for (int r = 0; r < R; r++) {
        const float* p = inp + (long)rows[r] * OBS;
        for (int i = lane; i < OBS; i += 32) s[r][S_RAW + i] = p[i];
    }
    __syncwarp();

    // ---- self encoder: 4 -> 100 ----
    {
        pf4 w0 = pz(), w1 = pz(), w2 = pz(), w3 = pz(), bp = pz();
        float4 g4 = f4z(), be4 = f4z();
        if (act) {
            w0 = ldp(sW + j0); w1 = ldp(sW + HD + j0); w2 = ldp(sW + 2 * HD + j0); w3 = ldp(sW + 3 * HD + j0);
            bp = ldp(sb + j0);
            g4 = ld4(sg + j0); be4 = ld4(sbe + j0);
        }
#pragma unroll
        for (int r = 0; r < R; r++) {
            pf4 p = bp;
            fmap(pk(s[r][S_RAW + 0]), w0, p);
            fmap(pk(s[r][S_RAW + 1]), w1, p);
            fmap(pk(s[r][S_RAW + 2]), w2, p);
            fmap(pk(s[r][S_RAW + 3]), w3, p);
            float4 e = ln4(tanh4h(upk(p)), g4, be4, act);
            if (act) st4(s[r] + S_SE + j0, e);
        }
    }
    __syncwarp();

    // ---- fused 100x100 matvecs (4-row blocked, packed): qa = se@Ac, ql = se@Lc, gp = se@fcW ----
    pf4 qa[R], ql[R], gp[R];
#pragma unroll
    for (int r = 0; r < R; r++) { qa[r] = pz(); ql[r] = pz(); gp[r] = pz(); }
    if (act) {
        pf4 bpfc = ldp(fcb + j0);
#pragma unroll
        for (int r = 0; r < R; r++) gp[r] = bpfc;
#pragma unroll 2
        for (int k4 = 0; k4 < 25; k4++) {
            float4 xv[R];
#pragma unroll
            for (int r = 0; r < R; r++) xv[r] = ld4(s[r] + S_SE + 4 * k4);
#pragma unroll
            for (int kk = 0; kk < 4; kk++) {
                const int k = 4 * k4 + kk;
                pf4 wa = ldp(Ac + k * HD + j0);
                pf4 wl = ldp(Lc + k * HD + j0);
                pf4 wf = ldp(fcW + k * HD + j0);
#pragma unroll
                for (int r = 0; r < R; r++) {
                    u64 xs = pk(getc(xv[r], kk));
                    fmap(xs, wa, qa[r]);
                    fmap(xs, wl, ql[r]);
                    fmap(xs, wf, gp[r]);
                }
            }
        }
    }
    // gi -> x[0:100]
    {
        float4 g4 = f4z(), b4 = f4z();
        if (act) { g4 = ld4(fcg + j0); b4 = ld4(fcbe + j0); }
#pragma unroll
        for (int r = 0; r < R; r++) {
            float4 gi = ln4(tanh4h(upk(gp[r])), g4, b4, act);
            if (act) st4(s[r] + S_X + j0, gi);
        }
    }
    __syncwarp();

    // ---- attention heads (2 rows per call; ql reused for goal head: source bug preserved) ----
    {
        float4 qaF[R], qlF[R];
#pragma unroll
        for (int r = 0; r < R; r++) { qaF[r] = upk(qa[r]); qlF[r] = upk(ql[r]); }
        attn_head<2, 15>(s[0], s[1], smem + TB_O, qaF[0], qaF[1], S_RAW + 52, oW, ob, og, obe, 100, act, lane, j0);
        attn_head<2, 15>(s[2], s[3], smem + TB_O, qaF[2], qaF[3], S_RAW + 52, oW, ob, og, obe, 100, act, lane, j0);
        attn_head<3, 16>(s[0], s[1], smem + TB_L, qlF[0], qlF[1], S_RAW + 4,  lW, lb, lg, lbe, 200, act, lane, j0);
        attn_head<3, 16>(s[2], s[3], smem + TB_L, qlF[2], qlF[3], S_RAW + 4,  lW, lb, lg, lbe, 200, act, lane, j0);
        attn_head<2, 16>(s[0], s[1], smem + TB_G, qlF[0], qlF[1], S_RAW + 82, gW, gb, gg, gbe, 300, act, lane, j0);
        attn_head<2, 16>(s[2], s[3], smem + TB_G, qlF[2], qlF[3], S_RAW + 82, gW, gb, gg, gbe, 300, act, lane, j0);
    }

    // ---- f1: 400 -> 100 (4-row blocked, packed) ----
    {
        pf4 a[R];
#pragma unroll
        for (int r = 0; r < R; r++) a[r] = pz();
        if (act) {
            pf4 bp = ldp(f1b + j0);
#pragma unroll
            for (int r = 0; r < R; r++) a[r] = bp;
#pragma unroll 2
            for (int k4 = 0; k4 < 100; k4++) {
                float4 xv[R];
#pragma unroll
                for (int r = 0; r < R; r++) xv[r] = ld4(s[r] + S_X + 4 * k4);
#pragma unroll
                for (int kk = 0; kk < 4; kk++) {
                    pf4 w = ldp(f1W + (4 * k4 + kk) * HD + j0);
#pragma unroll
                    for (int r = 0; r < R; r++) fmap(pk(getc(xv[r], kk)), w, a[r]);
                }
            }
        }
        float4 g4 = f4z(), b4 = f4z();
        if (act) { g4 = ld4(f1g + j0); b4 = ld4(f1be + j0); }
#pragma unroll
        for (int r = 0; r < R; r++) {
            float4 h = ln4(tanh4h(upk(a[r])), g4, b4, act);
            if (act) st4(s[r] + S_H + j0, h);
        }
    }
    __syncwarp();

    // ---- f2: 100 -> 100 -> out ----
    {
        pf4 a[R];
#pragma unroll
        for (int r = 0; r < R; r++) a[r] = pz();
        if (act) {
            pf4 bp = ldp(f2b + j0);
#pragma unroll
            for (int r = 0; r < R; r++) a[r] = bp;
#pragma unroll 2
            for (int k4 = 0; k4 < 25; k4++) {
                float4 xv[R];
#pragma unroll
                for (int r = 0; r < R; r++) xv[r] = ld4(s[r] + S_H + 4 * k4);
#pragma unroll
                for (int kk = 0; kk < 4; kk++) {
                    pf4 w = ldp(f2W + (4 * k4 + kk) * HD + j0);
#pragma unroll
                    for (int r = 0; r < R; r++) fmap(pk(getc(xv[r], kk)), w, a[r]);
                }
            }
        }
        float4 g4 = f4z(), b4 = f4z();
        if (act) { g4 = ld4(f2g + j0); b4 = ld4(f2be + j0); }
#pragma unroll
        for (int r = 0; r < R; r++) {
            float4 o = ln4(tanh4h(upk(a[r])), g4, b4, act);
            if (act) st4(out + (long)rows[r] * HD + j0, o);
        }
    }
}

extern "C" void kernel_launch(void* const* d_in, const int* in_sizes, int n_in,
                              void* d_out, int out_size) {
    const float* inp = (const float*)d_in[0];
    const int B = in_sizes[0] / OBS;

    cudaFuncSetAttribute(obsenc_kernel, cudaFuncAttributeMaxDynamicSharedMemorySize, SMEM_BYTES);

    const int rowsPerBlock = RPB * R;
    dim3 grid((B + rowsPerBlock - 1) / rowsPerBlock);
    obsenc_kernel<<<grid, RPB * 32, SMEM_BYTES>>>(
        inp, B,
        (const float*)d_in[2],  (const float*)d_in[3],  (const float*)d_in[4],  (const float*)d_in[5],
        (const float*)d_in[6],  (const float*)d_in[7],  (const float*)d_in[8],  (const float*)d_in[9],
        (const float*)d_in[10], (const float*)d_in[11], (const float*)d_in[12], (const float*)d_in[13],
        (const float*)d_in[14], (const float*)d_in[15], (const float*)d_in[16], (const float*)d_in[17],
        (const float*)d_in[18], (const float*)d_in[19],
        (const float*)d_in[20], (const float*)d_in[21], (const float*)d_in[22], (const float*)d_in[23],
        (const float*)d_in[24], (const float*)d_in[25], (const float*)d_in[26], (const float*)d_in[27],
        (const float*)d_in[28], (const float*)d_in[29], (const float*)d_in[30], (const float*)d_in[31],
        (float*)d_out);
}